// round 6
// baseline (speedup 1.0000x reference)
#include <cuda_runtime.h>
#include <cuda_bf16.h>
#include <math.h>
#include <stdint.h>

// ---------------- problem constants ----------------
#define N_MICRO_MAX 500000
#define MICRO_DIM   512
#define N_NODES_C   20000
#define N_EDGES_C   40000
#define NSEG        60000
#define NSEG_PAD    60032          // 938 * 64
#define EPS_SM      1e-8f
#define EPS_LN      1e-5f

#define CHUNK       1024
#define NB_CHUNK    59

#define CACHE_ROWS  12
#define MAX_SH      1024

// ---------------- device scratch ----------------
__device__ int   g_counts[NSEG];
__device__ int   g_offsets[NSEG];
__device__ int   g_cursor[NSEG];
__device__ int   g_bsum[NB_CHUNK];
__device__ int   g_rows[N_MICRO_MAX];
__device__ __align__(128) __nv_bfloat16 g_a_hi[(size_t)NSEG_PAD * MICRO_DIM];  // A bf16 hi (zero-init pad)
__device__ __align__(128) __nv_bfloat16 g_a_lo[(size_t)NSEG_PAD * MICRO_DIM];  // A bf16 lo
__device__ __align__(128) __nv_bfloat16 g_wt_hi[MICRO_DIM * MICRO_DIM];        // W^T [N][K], bf16 hi
__device__ __align__(128) __nv_bfloat16 g_wt_lo[MICRO_DIM * MICRO_DIM];        // W^T [N][K], bf16 lo

// ---------------- helpers ----------------
__device__ __forceinline__ uint32_t smem_u32(const void* p) {
    uint32_t a;
    asm("{ .reg .u64 t; cvta.to.shared.u64 t, %1; cvt.u32.u64 %0, t; }" : "=r"(a) : "l"(p));
    return a;
}

__device__ __forceinline__ int seg_of(int m) {
    if (m >= 0) return m;
    if (m == -100) return -1;
    return N_NODES_C + (-m - 1);
}

__device__ __forceinline__ void ldsm4(uint32_t* r, uint32_t addr) {
    asm volatile("ldmatrix.sync.aligned.m8n8.x4.shared.b16 {%0,%1,%2,%3}, [%4];"
        : "=r"(r[0]), "=r"(r[1]), "=r"(r[2]), "=r"(r[3]) : "r"(addr));
}

__device__ __forceinline__ void mma_bf16(float* d, const uint32_t* a, const uint32_t* b) {
    asm volatile("mma.sync.aligned.m16n8k16.row.col.f32.bf16.bf16.f32 "
        "{%0,%1,%2,%3},{%4,%5,%6,%7},{%8,%9},{%0,%1,%2,%3};"
        : "+f"(d[0]), "+f"(d[1]), "+f"(d[2]), "+f"(d[3])
        : "r"(a[0]), "r"(a[1]), "r"(a[2]), "r"(a[3]), "r"(b[0]), "r"(b[1]));
}

#define CP_ASYNC16(dst, src) \
    asm volatile("cp.async.cg.shared.global [%0], [%1], 16;" :: "r"(dst), "l"(src))
#define CP_COMMIT() asm volatile("cp.async.commit_group;" ::: "memory")
#define CP_WAIT1()  asm volatile("cp.async.wait_group 1;" ::: "memory")
#define CP_WAIT0()  asm volatile("cp.async.wait_group 0;" ::: "memory")

__device__ __forceinline__ float gelu_exact(float y) {
    return 0.5f * y * (1.f + erff(y * 0.70710678118654752f));
}

// ---------------- 0) init scratch ----------------
__global__ void init_kernel() {
    int i = blockIdx.x * blockDim.x + threadIdx.x;
    if (i < NSEG) { g_counts[i] = 0; g_cursor[i] = 0; }
}

// ---------------- 1) count ----------------
__global__ void count_kernel(const int* __restrict__ m2m, int n) {
    int i = blockIdx.x * blockDim.x + threadIdx.x;
    if (i < n) {
        int s = seg_of(m2m[i]);
        if (s >= 0) atomicAdd(&g_counts[s], 1);
    }
}

// ---------------- 2) scan ----------------
__global__ void sum_chunks_kernel() {
    __shared__ int sh[256];
    int b = blockIdx.x, t = threadIdx.x;
    int base = b * CHUNK;
    int s = 0;
    for (int j = t; j < CHUNK; j += 256) {
        int i = base + j;
        if (i < NSEG) s += g_counts[i];
    }
    sh[t] = s; __syncthreads();
    for (int d = 128; d; d >>= 1) { if (t < d) sh[t] += sh[t + d]; __syncthreads(); }
    if (t == 0) g_bsum[b] = sh[0];
}

__global__ void scan_bsums_kernel() {
    if (threadIdx.x == 0 && blockIdx.x == 0) {
        int c = 0;
        for (int b = 0; b < NB_CHUNK; b++) { int v = g_bsum[b]; g_bsum[b] = c; c += v; }
    }
}

__global__ void scan_chunks_kernel() {
    int b = blockIdx.x, lane = threadIdx.x;
    int base = b * CHUNK + lane * 32;
    int vals[32];
    int lsum = 0;
    #pragma unroll
    for (int j = 0; j < 32; j++) {
        int i = base + j;
        vals[j] = (i < NSEG) ? g_counts[i] : 0;
        lsum += vals[j];
    }
    int pre = lsum;
    #pragma unroll
    for (int d = 1; d < 32; d <<= 1) {
        int x = __shfl_up_sync(0xffffffffu, pre, d);
        if (lane >= d) pre += x;
    }
    pre -= lsum;
    int carry = g_bsum[b] + pre;
    #pragma unroll
    for (int j = 0; j < 32; j++) {
        int i = base + j;
        if (i < NSEG) g_offsets[i] = carry;
        carry += vals[j];
    }
}

// ---------------- 3) scatter ----------------
__global__ void scatter_kernel(const int* __restrict__ m2m, int n) {
    int i = blockIdx.x * blockDim.x + threadIdx.x;
    if (i < n) {
        int s = seg_of(m2m[i]);
        if (s >= 0) {
            int pos = g_offsets[s] + atomicAdd(&g_cursor[s], 1);
            g_rows[pos] = i;
        }
    }
}

// ---------------- 3b) W transpose + bf16 hi/lo split ----------------
__global__ void wsplit_kernel(const float* __restrict__ W) {
    int i = blockIdx.x * blockDim.x + threadIdx.x;   // i = k*512 + n
    int k = i >> 9, n = i & 511;
    float v = W[i];
    __nv_bfloat16 hi = __float2bfloat16_rn(v);
    __nv_bfloat16 lo = __float2bfloat16_rn(v - __bfloat162float(hi));
    g_wt_hi[n * MICRO_DIM + k] = hi;
    g_wt_lo[n * MICRO_DIM + k] = lo;
}

// ---------------- 4) per-segment fused softmax aggregation ----------------
__global__ void __launch_bounds__(256, 6)
agg_kernel(const float* __restrict__ feat,
           const float* __restrict__ attn_w,
           const float* __restrict__ attn_bp) {
    __shared__ float s_aw[MICRO_DIM];
    __shared__ float s_rows[CACHE_ROWS][MICRO_DIM];
    __shared__ float s_logit[MAX_SH];
    __shared__ float s_red[8];

    int seg  = blockIdx.x;
    int tid  = threadIdx.x;
    int lane = tid & 31, wid = tid >> 5;
    int cnt  = g_counts[seg];
    int off  = g_offsets[seg];
    int c0 = tid, c1 = tid + 256;
    size_t outbase = (size_t)seg * MICRO_DIM;

    if (cnt == 0) {
        __nv_bfloat16 z = __float2bfloat16_rn(0.f);
        g_a_hi[outbase + c0] = z;
        g_a_hi[outbase + c1] = z;
        g_a_lo[outbase + c0] = z;
        g_a_lo[outbase + c1] = z;
        return;
    }

    for (int j = tid; j < MICRO_DIM; j += 256) s_aw[j] = attn_w[j];
    __syncthreads();
    float ab = attn_bp[0];
    float acc0 = 0.f, acc1 = 0.f;

    if (cnt <= MAX_SH) {
        for (int r = wid; r < cnt; r += 8) {
            int row = g_rows[off + r];
            const float4* fp = (const float4*)(feat + (size_t)row * MICRO_DIM);
            float dot = 0.f;
            bool cache = (r < CACHE_ROWS);
            #pragma unroll
            for (int k = 0; k < 4; k++) {
                float4 v = fp[lane + 32 * k];
                int j = (lane + 32 * k) * 4;
                dot += v.x * s_aw[j] + v.y * s_aw[j + 1] + v.z * s_aw[j + 2] + v.w * s_aw[j + 3];
                if (cache) ((float4*)s_rows[r])[lane + 32 * k] = v;
            }
            #pragma unroll
            for (int d = 16; d; d >>= 1) dot += __shfl_xor_sync(0xffffffffu, dot, d);
            if (lane == 0) s_logit[r] = dot + ab;
        }
        __syncthreads();

        float m = -INFINITY;
        for (int r = tid; r < cnt; r += 256) m = fmaxf(m, s_logit[r]);
        #pragma unroll
        for (int d = 16; d; d >>= 1) m = fmaxf(m, __shfl_xor_sync(0xffffffffu, m, d));
        if (lane == 0) s_red[wid] = m;
        __syncthreads();
        m = s_red[0];
        #pragma unroll
        for (int w = 1; w < 8; w++) m = fmaxf(m, s_red[w]);
        __syncthreads();

        float ssum = 0.f;
        for (int r = tid; r < cnt; r += 256) {
            float e = expf(s_logit[r] - m);
            s_logit[r] = e;
            ssum += e;
        }
        #pragma unroll
        for (int d = 16; d; d >>= 1) ssum += __shfl_xor_sync(0xffffffffu, ssum, d);
        if (lane == 0) s_red[wid] = ssum;
        __syncthreads();
        float tot = 0.f;
        #pragma unroll
        for (int w = 0; w < 8; w++) tot += s_red[w];
        float inv = 1.f / (tot + EPS_SM);

        for (int r = 0; r < cnt; r++) {
            float wgt = s_logit[r] * inv;
            if (r < CACHE_ROWS) {
                acc0 += wgt * s_rows[r][c0];
                acc1 += wgt * s_rows[r][c1];
            } else {
                int row = g_rows[off + r];
                acc0 += wgt * __ldg(feat + (size_t)row * MICRO_DIM + c0);
                acc1 += wgt * __ldg(feat + (size_t)row * MICRO_DIM + c1);
            }
        }
    } else {
        float m = -INFINITY, s = 0.f;
        for (int r = 0; r < cnt; r++) {
            int row = g_rows[off + r];
            const float* f = feat + (size_t)row * MICRO_DIM;
            float f0 = f[c0], f1 = f[c1];
            float p = f0 * s_aw[c0] + f1 * s_aw[c1];
            #pragma unroll
            for (int d = 16; d; d >>= 1) p += __shfl_xor_sync(0xffffffffu, p, d);
            if (lane == 0) s_red[wid] = p;
            __syncthreads();
            float l = ab;
            #pragma unroll
            for (int w = 0; w < 8; w++) l += s_red[w];
            __syncthreads();
            float mn = fmaxf(m, l);
            float sc = expf(m - mn);
            float e  = expf(l - mn);
            s    = s * sc + e;
            acc0 = acc0 * sc + e * f0;
            acc1 = acc1 * sc + e * f1;
            m = mn;
        }
        float inv = 1.f / (s + EPS_SM);
        acc0 *= inv; acc1 *= inv;
    }

    __nv_bfloat16 h0 = __float2bfloat16_rn(acc0);
    __nv_bfloat16 h1 = __float2bfloat16_rn(acc1);
    g_a_hi[outbase + c0] = h0;
    g_a_hi[outbase + c1] = h1;
    g_a_lo[outbase + c0] = __float2bfloat16_rn(acc0 - __bfloat162float(h0));
    g_a_lo[outbase + c1] = __float2bfloat16_rn(acc1 - __bfloat162float(h1));
}

// ---------------- 5) fused GEMM + bias + LayerNorm + GELU ----------------
// CTA tile 64x512 (full output rows), 512 threads, 16 warps = 4 m-slices x 4 n-slices.
// Warp tile 16x128. 3-term bf16 split. 2-stage cp.async pipeline. LN in epilogue.
#define GT_M     64
#define GKC      32
#define GNCHUNK  16
#define ROWB     80
#define AHI_OFF  0                       // 64*80   = 5120
#define ALO_OFF  5120
#define BHI_OFF  10240                   // 512*80  = 40960
#define BLO_OFF  51200
#define STAGE_SZ 92160
#define STAT_OFF (2 * STAGE_SZ)          // 184320: 4 warp_n x 64 rows x 2 floats
#define SMEM_GF  (2 * STAGE_SZ + 2048)   // 186368

__global__ void __launch_bounds__(512)
gemm_fused_kernel(const float* __restrict__ pb,
                  const float* __restrict__ lng,
                  const float* __restrict__ lnb,
                  float* __restrict__ out, int M) {
    extern __shared__ char smem[];
    uint32_t sbase = smem_u32(smem);

    int tid  = threadIdx.x;
    int lane = tid & 31, wid = tid >> 5;
    int warp_m = wid & 3;          // 16-row slice
    int warp_n = wid >> 2;         // 128-col slice
    int rowBase = blockIdx.x * GT_M;

    float acc[16][4];
    #pragma unroll
    for (int j = 0; j < 16; j++)
        #pragma unroll
        for (int q = 0; q < 4; q++) acc[j][q] = 0.f;

    // cp.async issue: slot 0 = A (256 hi + 256 lo copies), slots 1..8 = B (4096 copies)
    #define GF_ISSUE(c) do {                                                         \
        uint32_t sb_ = sbase + ((c) & 1) * STAGE_SZ;                                 \
        int k0_ = (c) * GKC;                                                         \
        {                                                                            \
            int r_ = (tid & 255) >> 2, q_ = tid & 3;                                 \
            const __nv_bfloat16* s_ = ((tid < 256) ? g_a_hi : g_a_lo)                \
                + (size_t)(rowBase + r_) * MICRO_DIM + q_ * 8 + k0_;                 \
            uint32_t d_ = sb_ + ((tid < 256) ? AHI_OFF : ALO_OFF) + r_ * ROWB + q_ * 16; \
            CP_ASYNC16(d_, s_);                                                      \
        }                                                                            \
        _Pragma("unroll")                                                            \
        for (int i_ = 0; i_ < 8; i_++) {                                             \
            int w_ = tid + i_ * 512;                                                 \
            int hi_ = (w_ < 2048) ? 1 : 0;                                           \
            int w2_ = w_ & 2047;                                                     \
            int r_ = w2_ >> 2, q_ = w2_ & 3;                                         \
            const __nv_bfloat16* s_ = (hi_ ? g_wt_hi : g_wt_lo)                      \
                + (size_t)r_ * MICRO_DIM + q_ * 8 + k0_;                             \
            uint32_t d_ = sb_ + (hi_ ? BHI_OFF : BLO_OFF) + r_ * ROWB + q_ * 16;     \
            CP_ASYNC16(d_, s_);                                                      \
        }                                                                            \
        CP_COMMIT();                                                                 \
    } while (0)

    // ldmatrix lane addressing
    int a_r = (lane & 7) + ((lane >> 3) & 1) * 8;
    int a_o = (lane >> 4) * 16;
    int b_r = (lane & 7) + ((lane >> 4) & 1) * 8;
    int b_o = ((lane >> 3) & 1) * 16;

    GF_ISSUE(0);

    for (int c = 0; c < GNCHUNK; c++) {
        if (c + 1 < GNCHUNK) { GF_ISSUE(c + 1); CP_WAIT1(); }
        else                 { CP_WAIT0(); }
        __syncthreads();

        uint32_t stage = sbase + (c & 1) * STAGE_SZ;
        #pragma unroll
        for (int s = 0; s < 2; s++) {
            uint32_t ah[4], al[4];
            uint32_t aoff = (uint32_t)((warp_m * 16 + a_r) * ROWB + s * 32 + a_o);
            ldsm4(ah, stage + AHI_OFF + aoff);
            ldsm4(al, stage + ALO_OFF + aoff);
            #pragma unroll
            for (int p = 0; p < 8; p++) {
                uint32_t bh[4], bl[4];
                uint32_t boff = (uint32_t)((warp_n * 128 + p * 16 + b_r) * ROWB + s * 32 + b_o);
                ldsm4(bh, stage + BHI_OFF + boff);
                ldsm4(bl, stage + BLO_OFF + boff);
                mma_bf16(acc[2 * p],     ah, &bh[0]);
                mma_bf16(acc[2 * p + 1], ah, &bh[2]);
                mma_bf16(acc[2 * p],     ah, &bl[0]);
                mma_bf16(acc[2 * p + 1], ah, &bl[2]);
                mma_bf16(acc[2 * p],     al, &bh[0]);
                mma_bf16(acc[2 * p + 1], al, &bh[2]);
            }
        }
        __syncthreads();
    }

    // ---- epilogue: bias + LN stats (quad shuffle + smem across warp_n) + GELU ----
    int r0 = warp_m * 16 + (lane >> 2);      // tile-local rows
    int r1 = r0 + 8;
    float s0 = 0.f, q0 = 0.f, s1 = 0.f, q1 = 0.f;
    #pragma unroll
    for (int nt = 0; nt < 16; nt++) {
        int col = warp_n * 128 + nt * 8 + (lane & 3) * 2;
        float2 b2 = *(const float2*)(pb + col);
        acc[nt][0] += b2.x; acc[nt][1] += b2.y;
        acc[nt][2] += b2.x; acc[nt][3] += b2.y;
        s0 += acc[nt][0] + acc[nt][1];
        q0 += acc[nt][0] * acc[nt][0] + acc[nt][1] * acc[nt][1];
        s1 += acc[nt][2] + acc[nt][3];
        q1 += acc[nt][2] * acc[nt][2] + acc[nt][3] * acc[nt][3];
    }
    #pragma unroll
    for (int d = 1; d < 4; d <<= 1) {
        s0 += __shfl_xor_sync(0xffffffffu, s0, d);
        q0 += __shfl_xor_sync(0xffffffffu, q0, d);
        s1 += __shfl_xor_sync(0xffffffffu, s1, d);
        q1 += __shfl_xor_sync(0xffffffffu, q1, d);
    }
    float* st = (float*)(smem + STAT_OFF);
    if ((lane & 3) == 0) {
        st[(warp_n * 64 + r0) * 2 + 0] = s0;
        st[(warp_n * 64 + r0) * 2 + 1] = q0;
        st[(warp_n * 64 + r1) * 2 + 0] = s1;
        st[(warp_n * 64 + r1) * 2 + 1] = q1;
    }
    __syncthreads();

    float sS0 = 0.f, sQ0 = 0.f, sS1 = 0.f, sQ1 = 0.f;
    #pragma unroll
    for (int wn = 0; wn < 4; wn++) {
        sS0 += st[(wn * 64 + r0) * 2 + 0];
        sQ0 += st[(wn * 64 + r0) * 2 + 1];
        sS1 += st[(wn * 64 + r1) * 2 + 0];
        sQ1 += st[(wn * 64 + r1) * 2 + 1];
    }
    float mu0 = sS0 * (1.f / 512.f);
    float mu1 = sS1 * (1.f / 512.f);
    float rs0 = rsqrtf(sQ0 * (1.f / 512.f) - mu0 * mu0 + EPS_LN);
    float rs1 = rsqrtf(sQ1 * (1.f / 512.f) - mu1 * mu1 + EPS_LN);

    int gr0 = rowBase + r0, gr1 = rowBase + r1;
    bool ok0 = gr0 < M, ok1 = gr1 < M;
    float* o0 = out + (size_t)gr0 * MICRO_DIM;
    float* o1 = out + (size_t)gr1 * MICRO_DIM;
    #pragma unroll
    for (int nt = 0; nt < 16; nt++) {
        int col = warp_n * 128 + nt * 8 + (lane & 3) * 2;
        float2 gg = *(const float2*)(lng + col);
        float2 bb = *(const float2*)(lnb + col);
        if (ok0) {
            float y0 = (acc[nt][0] - mu0) * rs0 * gg.x + bb.x;
            float y1 = (acc[nt][1] - mu0) * rs0 * gg.y + bb.y;
            *(float2*)(o0 + col) = make_float2(gelu_exact(y0), gelu_exact(y1));
        }
        if (ok1) {
            float y2 = (acc[nt][2] - mu1) * rs1 * gg.x + bb.x;
            float y3 = (acc[nt][3] - mu1) * rs1 * gg.y + bb.y;
            *(float2*)(o1 + col) = make_float2(gelu_exact(y2), gelu_exact(y3));
        }
    }
    #undef GF_ISSUE
}

// ---------------- launch ----------------
extern "C" void kernel_launch(void* const* d_in, const int* in_sizes, int n_in,
                              void* d_out, int out_size) {
    const float* feat   = (const float*)d_in[0];
    const float* attn_w = (const float*)d_in[1];
    const float* attn_b = (const float*)d_in[2];
    const float* proj_w = (const float*)d_in[3];
    const float* proj_b = (const float*)d_in[4];
    const float* ln_g   = (const float*)d_in[5];
    const float* ln_b   = (const float*)d_in[6];
    const int*   m2m    = (const int*)d_in[7];
    int n = in_sizes[7];
    float* out = (float*)d_out;

    static bool attr_done = false;
    if (!attr_done) {
        cudaFuncSetAttribute(gemm_fused_kernel,
                             cudaFuncAttributeMaxDynamicSharedMemorySize, SMEM_GF);
        attr_done = true;
    }

    init_kernel<<<(NSEG + 255) / 256, 256>>>();
    count_kernel<<<(n + 255) / 256, 256>>>(m2m, n);
    sum_chunks_kernel<<<NB_CHUNK, 256>>>();
    scan_bsums_kernel<<<1, 32>>>();
    scan_chunks_kernel<<<NB_CHUNK, 32>>>();
    scatter_kernel<<<(n + 255) / 256, 256>>>(m2m, n);
    wsplit_kernel<<<(MICRO_DIM * MICRO_DIM) / 256, 256>>>(proj_w);
    agg_kernel<<<NSEG, 256>>>(feat, attn_w, attn_b);

    gemm_fused_kernel<<<NSEG_PAD / GT_M, 512, SMEM_GF>>>(proj_b, ln_g, ln_b, out, NSEG);
}

// round 7
// speedup vs baseline: 1.1427x; 1.1427x over previous
#include <cuda_runtime.h>
#include <cuda_bf16.h>
#include <math.h>
#include <stdint.h>

// ---------------- problem constants ----------------
#define N_MICRO_MAX 500000
#define MICRO_DIM   512
#define N_NODES_C   20000
#define N_EDGES_C   40000
#define NSEG        60000
#define NSEG_PAD    60032          // 469 * 128
#define EPS_SM      1e-8f
#define EPS_LN      1e-5f

#define CHUNK       1024
#define NB_CHUNK    59

#define CACHE_ROWS  12
#define MAX_SH      1024

// ---------------- device scratch ----------------
__device__ int   g_counts[NSEG];
__device__ int   g_offsets[NSEG];
__device__ int   g_cursor[NSEG];
__device__ int   g_bsum[NB_CHUNK];
__device__ int   g_rows[N_MICRO_MAX];
__device__ __align__(128) __nv_bfloat16 g_a_hi[(size_t)NSEG_PAD * MICRO_DIM];  // A bf16 hi (zero-init pad)
__device__ __align__(128) __nv_bfloat16 g_a_lo[(size_t)NSEG_PAD * MICRO_DIM];  // A bf16 lo
__device__ __align__(128) __nv_bfloat16 g_wt_hi[MICRO_DIM * MICRO_DIM];        // W^T [N][K], bf16 hi
__device__ __align__(128) __nv_bfloat16 g_wt_lo[MICRO_DIM * MICRO_DIM];        // W^T [N][K], bf16 lo

// ---------------- helpers ----------------
__device__ __forceinline__ uint32_t smem_u32(const void* p) {
    uint32_t a;
    asm("{ .reg .u64 t; cvta.to.shared.u64 t, %1; cvt.u32.u64 %0, t; }" : "=r"(a) : "l"(p));
    return a;
}

__device__ __forceinline__ int seg_of(int m) {
    if (m >= 0) return m;
    if (m == -100) return -1;
    return N_NODES_C + (-m - 1);
}

__device__ __forceinline__ void ldsm4(uint32_t* r, uint32_t addr) {
    asm volatile("ldmatrix.sync.aligned.m8n8.x4.shared.b16 {%0,%1,%2,%3}, [%4];"
        : "=r"(r[0]), "=r"(r[1]), "=r"(r[2]), "=r"(r[3]) : "r"(addr));
}

__device__ __forceinline__ void mma_bf16(float* d, const uint32_t* a, const uint32_t* b) {
    asm volatile("mma.sync.aligned.m16n8k16.row.col.f32.bf16.bf16.f32 "
        "{%0,%1,%2,%3},{%4,%5,%6,%7},{%8,%9},{%0,%1,%2,%3};"
        : "+f"(d[0]), "+f"(d[1]), "+f"(d[2]), "+f"(d[3])
        : "r"(a[0]), "r"(a[1]), "r"(a[2]), "r"(a[3]), "r"(b[0]), "r"(b[1]));
}

#define CP_ASYNC16(dst, src) \
    asm volatile("cp.async.cg.shared.global [%0], [%1], 16;" :: "r"(dst), "l"(src))
#define CP_COMMIT() asm volatile("cp.async.commit_group;" ::: "memory")
#define CP_WAITG(n) asm volatile("cp.async.wait_group %0;" :: "n"(n) : "memory")

__device__ __forceinline__ float gelu_exact(float y) {
    return 0.5f * y * (1.f + erff(y * 0.70710678118654752f));
}

// ---------------- 0) init scratch + W transpose/split (merged) ----------------
__global__ void init_wsplit_kernel(const float* __restrict__ W) {
    int i = blockIdx.x * blockDim.x + threadIdx.x;   // 0 .. 262143
    if (i < NSEG) { g_counts[i] = 0; g_cursor[i] = 0; }
    int k = i >> 9, n = i & 511;
    float v = W[i];
    __nv_bfloat16 hi = __float2bfloat16_rn(v);
    __nv_bfloat16 lo = __float2bfloat16_rn(v - __bfloat162float(hi));
    g_wt_hi[n * MICRO_DIM + k] = hi;
    g_wt_lo[n * MICRO_DIM + k] = lo;
}

// ---------------- 1) count ----------------
__global__ void count_kernel(const int* __restrict__ m2m, int n) {
    int i = blockIdx.x * blockDim.x + threadIdx.x;
    if (i < n) {
        int s = seg_of(m2m[i]);
        if (s >= 0) atomicAdd(&g_counts[s], 1);
    }
}

// ---------------- 2) scan ----------------
__global__ void sum_chunks_kernel() {
    __shared__ int sh[256];
    int b = blockIdx.x, t = threadIdx.x;
    int base = b * CHUNK;
    int s = 0;
    for (int j = t; j < CHUNK; j += 256) {
        int i = base + j;
        if (i < NSEG) s += g_counts[i];
    }
    sh[t] = s; __syncthreads();
    for (int d = 128; d; d >>= 1) { if (t < d) sh[t] += sh[t + d]; __syncthreads(); }
    if (t == 0) g_bsum[b] = sh[0];
}

__global__ void scan_bsums_kernel() {
    if (threadIdx.x == 0 && blockIdx.x == 0) {
        int c = 0;
        for (int b = 0; b < NB_CHUNK; b++) { int v = g_bsum[b]; g_bsum[b] = c; c += v; }
    }
}

__global__ void scan_chunks_kernel() {
    int b = blockIdx.x, lane = threadIdx.x;
    int base = b * CHUNK + lane * 32;
    int vals[32];
    int lsum = 0;
    #pragma unroll
    for (int j = 0; j < 32; j++) {
        int i = base + j;
        vals[j] = (i < NSEG) ? g_counts[i] : 0;
        lsum += vals[j];
    }
    int pre = lsum;
    #pragma unroll
    for (int d = 1; d < 32; d <<= 1) {
        int x = __shfl_up_sync(0xffffffffu, pre, d);
        if (lane >= d) pre += x;
    }
    pre -= lsum;
    int carry = g_bsum[b] + pre;
    #pragma unroll
    for (int j = 0; j < 32; j++) {
        int i = base + j;
        if (i < NSEG) g_offsets[i] = carry;
        carry += vals[j];
    }
}

// ---------------- 3) scatter ----------------
__global__ void scatter_kernel(const int* __restrict__ m2m, int n) {
    int i = blockIdx.x * blockDim.x + threadIdx.x;
    if (i < n) {
        int s = seg_of(m2m[i]);
        if (s >= 0) {
            int pos = g_offsets[s] + atomicAdd(&g_cursor[s], 1);
            g_rows[pos] = i;
        }
    }
}

// ---------------- 4) per-segment fused softmax aggregation ----------------
__global__ void __launch_bounds__(256, 6)
agg_kernel(const float* __restrict__ feat,
           const float* __restrict__ attn_w,
           const float* __restrict__ attn_bp) {
    __shared__ float s_aw[MICRO_DIM];
    __shared__ float s_rows[CACHE_ROWS][MICRO_DIM];
    __shared__ float s_logit[MAX_SH];
    __shared__ float s_red[8];

    int seg  = blockIdx.x;
    int tid  = threadIdx.x;
    int lane = tid & 31, wid = tid >> 5;
    int cnt  = g_counts[seg];
    int off  = g_offsets[seg];
    int c0 = tid, c1 = tid + 256;
    size_t outbase = (size_t)seg * MICRO_DIM;

    if (cnt == 0) {
        __nv_bfloat16 z = __float2bfloat16_rn(0.f);
        g_a_hi[outbase + c0] = z;
        g_a_hi[outbase + c1] = z;
        g_a_lo[outbase + c0] = z;
        g_a_lo[outbase + c1] = z;
        return;
    }

    for (int j = tid; j < MICRO_DIM; j += 256) s_aw[j] = attn_w[j];
    __syncthreads();
    float ab = attn_bp[0];
    float acc0 = 0.f, acc1 = 0.f;

    if (cnt <= MAX_SH) {
        for (int r = wid; r < cnt; r += 8) {
            int row = g_rows[off + r];
            const float4* fp = (const float4*)(feat + (size_t)row * MICRO_DIM);
            float dot = 0.f;
            bool cache = (r < CACHE_ROWS);
            #pragma unroll
            for (int k = 0; k < 4; k++) {
                float4 v = fp[lane + 32 * k];
                int j = (lane + 32 * k) * 4;
                dot += v.x * s_aw[j] + v.y * s_aw[j + 1] + v.z * s_aw[j + 2] + v.w * s_aw[j + 3];
                if (cache) ((float4*)s_rows[r])[lane + 32 * k] = v;
            }
            #pragma unroll
            for (int d = 16; d; d >>= 1) dot += __shfl_xor_sync(0xffffffffu, dot, d);
            if (lane == 0) s_logit[r] = dot + ab;
        }
        __syncthreads();

        float m = -INFINITY;
        for (int r = tid; r < cnt; r += 256) m = fmaxf(m, s_logit[r]);
        #pragma unroll
        for (int d = 16; d; d >>= 1) m = fmaxf(m, __shfl_xor_sync(0xffffffffu, m, d));
        if (lane == 0) s_red[wid] = m;
        __syncthreads();
        m = s_red[0];
        #pragma unroll
        for (int w = 1; w < 8; w++) m = fmaxf(m, s_red[w]);
        __syncthreads();

        float ssum = 0.f;
        for (int r = tid; r < cnt; r += 256) {
            float e = expf(s_logit[r] - m);
            s_logit[r] = e;
            ssum += e;
        }
        #pragma unroll
        for (int d = 16; d; d >>= 1) ssum += __shfl_xor_sync(0xffffffffu, ssum, d);
        if (lane == 0) s_red[wid] = ssum;
        __syncthreads();
        float tot = 0.f;
        #pragma unroll
        for (int w = 0; w < 8; w++) tot += s_red[w];
        float inv = 1.f / (tot + EPS_SM);

        for (int r = 0; r < cnt; r++) {
            float wgt = s_logit[r] * inv;
            if (r < CACHE_ROWS) {
                acc0 += wgt * s_rows[r][c0];
                acc1 += wgt * s_rows[r][c1];
            } else {
                int row = g_rows[off + r];
                acc0 += wgt * __ldg(feat + (size_t)row * MICRO_DIM + c0);
                acc1 += wgt * __ldg(feat + (size_t)row * MICRO_DIM + c1);
            }
        }
    } else {
        float m = -INFINITY, s = 0.f;
        for (int r = 0; r < cnt; r++) {
            int row = g_rows[off + r];
            const float* f = feat + (size_t)row * MICRO_DIM;
            float f0 = f[c0], f1 = f[c1];
            float p = f0 * s_aw[c0] + f1 * s_aw[c1];
            #pragma unroll
            for (int d = 16; d; d >>= 1) p += __shfl_xor_sync(0xffffffffu, p, d);
            if (lane == 0) s_red[wid] = p;
            __syncthreads();
            float l = ab;
            #pragma unroll
            for (int w = 0; w < 8; w++) l += s_red[w];
            __syncthreads();
            float mn = fmaxf(m, l);
            float sc = expf(m - mn);
            float e  = expf(l - mn);
            s    = s * sc + e;
            acc0 = acc0 * sc + e * f0;
            acc1 = acc1 * sc + e * f1;
            m = mn;
        }
        float inv = 1.f / (s + EPS_SM);
        acc0 *= inv; acc1 *= inv;
    }

    __nv_bfloat16 h0 = __float2bfloat16_rn(acc0);
    __nv_bfloat16 h1 = __float2bfloat16_rn(acc1);
    g_a_hi[outbase + c0] = h0;
    g_a_hi[outbase + c1] = h1;
    g_a_lo[outbase + c0] = __float2bfloat16_rn(acc0 - __bfloat162float(h0));
    g_a_lo[outbase + c1] = __float2bfloat16_rn(acc1 - __bfloat162float(h1));
}

// ---------------- 5) mma.sync bf16 3-split GEMM, 128x256 tile, 3-stage cp.async ----------------
#define GTILE_M   128
#define GTILE_N   256
#define GKC       32
#define GNCHUNK   16
#define ROWB      80
#define A_MAT     (128 * ROWB)       // 10240
#define B_MAT     (256 * ROWB)       // 20480
#define AHI_OFF   0
#define ALO_OFF   A_MAT
#define BHI_OFF   (2 * A_MAT)
#define BLO_OFF   (2 * A_MAT + B_MAT)
#define STAGE_SZ  (2 * A_MAT + 2 * B_MAT)   // 61440
#define NSTAGE    3
#define SMEM_GEMM (NSTAGE * STAGE_SZ)       // 184320

__global__ void __launch_bounds__(512, 1)
gemm_mma_kernel(float* __restrict__ out, int M) {
    extern __shared__ char smem[];
    uint32_t sbase = smem_u32(smem);

    int tid  = threadIdx.x;
    int lane = tid & 31, wid = tid >> 5;
    int warp_m = wid & 3;          // 32-row slice
    int warp_n = wid >> 2;         // 64-col slice (0..3)
    int rowBase = blockIdx.y * GTILE_M;
    int colBase = blockIdx.x * GTILE_N;

    float acc[2][8][4];
    #pragma unroll
    for (int i = 0; i < 2; i++)
        #pragma unroll
        for (int j = 0; j < 8; j++)
            #pragma unroll
            for (int q = 0; q < 4; q++) acc[i][j][q] = 0.f;

    // cp.async: A = 1024 16B copies (hi 512 + lo 512), B = 2048 (hi 1024 + lo 1024)
    #define G_ISSUE(c) do {                                                           \
        uint32_t sb_ = sbase + ((c) % NSTAGE) * STAGE_SZ;                             \
        int k0_ = (c) * GKC;                                                          \
        _Pragma("unroll")                                                             \
        for (int i_ = 0; i_ < 2; i_++) {                                              \
            int f_ = tid + i_ * 512;                                                  \
            int mat_ = f_ >> 9;  int w_ = f_ & 511;                                   \
            int r_ = w_ >> 2, q_ = w_ & 3;                                            \
            const __nv_bfloat16* s_ = (mat_ ? g_a_lo : g_a_hi)                        \
                + (size_t)(rowBase + r_) * MICRO_DIM + q_ * 8 + k0_;                  \
            CP_ASYNC16(sb_ + mat_ * A_MAT + r_ * ROWB + q_ * 16, s_);                 \
        }                                                                             \
        _Pragma("unroll")                                                             \
        for (int i_ = 0; i_ < 4; i_++) {                                              \
            int f_ = tid + i_ * 512;                                                  \
            int mat_ = f_ >> 10; int w_ = f_ & 1023;                                  \
            int r_ = w_ >> 2, q_ = w_ & 3;                                            \
            const __nv_bfloat16* s_ = (mat_ ? g_wt_lo : g_wt_hi)                      \
                + (size_t)(colBase + r_) * MICRO_DIM + q_ * 8 + k0_;                  \
            CP_ASYNC16(sb_ + BHI_OFF + mat_ * B_MAT + r_ * ROWB + q_ * 16, s_);       \
        }                                                                             \
        CP_COMMIT();                                                                  \
    } while (0)

    // ldmatrix lane addressing
    int a_r = (lane & 7) + ((lane >> 3) & 1) * 8;
    int a_o = (lane >> 4) * 16;
    int b_r = (lane & 7) + ((lane >> 4) & 1) * 8;
    int b_o = ((lane >> 3) & 1) * 16;

    G_ISSUE(0);
    G_ISSUE(1);

    for (int c = 0; c < GNCHUNK; c++) {
        CP_WAITG(1);            // stage c landed (c+1 may still be in flight)
        __syncthreads();

        uint32_t stage = sbase + (c % NSTAGE) * STAGE_SZ;
        #pragma unroll
        for (int s = 0; s < 2; s++) {
            uint32_t ah[2][4], al[2][4];
            #pragma unroll
            for (int mm = 0; mm < 2; mm++) {
                uint32_t off = (uint32_t)((warp_m * 32 + mm * 16 + a_r) * ROWB + s * 32 + a_o);
                ldsm4(ah[mm], stage + AHI_OFF + off);
                ldsm4(al[mm], stage + ALO_OFF + off);
            }
            #pragma unroll
            for (int p = 0; p < 4; p++) {
                uint32_t bh[4], bl[4];
                uint32_t off = (uint32_t)((warp_n * 64 + p * 16 + b_r) * ROWB + s * 32 + b_o);
                ldsm4(bh, stage + BHI_OFF + off);
                ldsm4(bl, stage + BLO_OFF + off);
                #pragma unroll
                for (int mm = 0; mm < 2; mm++) {
                    #pragma unroll
                    for (int h = 0; h < 2; h++) {          // nt = 2*p + h
                        float* a4 = acc[mm][2 * p + h];
                        mma_bf16(a4, ah[mm], &bh[h * 2]);
                        mma_bf16(a4, ah[mm], &bl[h * 2]);
                        mma_bf16(a4, al[mm], &bh[h * 2]);
                    }
                }
            }
        }
        // issue next-next chunk into the stage consumed at c-1 (all threads past the
        // sync at top of this iteration, so that buffer is free)
        if (c + 2 < GNCHUNK) G_ISSUE(c + 2);
    }

    // epilogue
    #pragma unroll
    for (int mm = 0; mm < 2; mm++) {
        int row0 = rowBase + warp_m * 32 + mm * 16 + (lane >> 2);
        #pragma unroll
        for (int nt = 0; nt < 8; nt++) {
            int col = colBase + warp_n * 64 + nt * 8 + (lane & 3) * 2;
            if (row0 < M)
                *(float2*)(out + (size_t)row0 * MICRO_DIM + col) =
                    make_float2(acc[mm][nt][0], acc[mm][nt][1]);
            if (row0 + 8 < M)
                *(float2*)(out + (size_t)(row0 + 8) * MICRO_DIM + col) =
                    make_float2(acc[mm][nt][2], acc[mm][nt][3]);
        }
    }
    #undef G_ISSUE
}

// ---------------- 6) bias + LayerNorm + exact GELU ----------------
__global__ void __launch_bounds__(256)
ln_gelu_kernel(const float* __restrict__ pb,
               const float* __restrict__ lng,
               const float* __restrict__ lnb,
               float* __restrict__ out, int M) {
    int row  = blockIdx.x * 8 + (threadIdx.x >> 5);
    int lane = threadIdx.x & 31;
    if (row >= M) return;

    float4* p = (float4*)(out + (size_t)row * MICRO_DIM);
    const float4* pb4 = (const float4*)pb;
    float x[16];
    float sum = 0.f;
    #pragma unroll
    for (int k = 0; k < 4; k++) {
        float4 h = p[lane + 32 * k];
        float4 b = pb4[lane + 32 * k];
        x[4*k+0] = h.x + b.x; x[4*k+1] = h.y + b.y;
        x[4*k+2] = h.z + b.z; x[4*k+3] = h.w + b.w;
        sum += x[4*k] + x[4*k+1] + x[4*k+2] + x[4*k+3];
    }
    #pragma unroll
    for (int d = 16; d; d >>= 1) sum += __shfl_xor_sync(0xffffffffu, sum, d);
    float mu = sum * (1.f / 512.f);

    float v = 0.f;
    #pragma unroll
    for (int i = 0; i < 16; i++) { float dlt = x[i] - mu; v += dlt * dlt; }
    #pragma unroll
    for (int d = 16; d; d >>= 1) v += __shfl_xor_sync(0xffffffffu, v, d);
    v *= (1.f / 512.f);
    float rs = rsqrtf(v + EPS_LN);

    const float4* g4 = (const float4*)lng;
    const float4* b4 = (const float4*)lnb;
    #pragma unroll
    for (int k = 0; k < 4; k++) {
        float4 gg = g4[lane + 32 * k];
        float4 bb = b4[lane + 32 * k];
        float4 o;
        float y;
        y = (x[4*k+0] - mu) * rs * gg.x + bb.x; o.x = gelu_exact(y);
        y = (x[4*k+1] - mu) * rs * gg.y + bb.y; o.y = gelu_exact(y);
        y = (x[4*k+2] - mu) * rs * gg.z + bb.z; o.z = gelu_exact(y);
        y = (x[4*k+3] - mu) * rs * gg.w + bb.w; o.w = gelu_exact(y);
        p[lane + 32 * k] = o;
    }
}

// ---------------- launch ----------------
extern "C" void kernel_launch(void* const* d_in, const int* in_sizes, int n_in,
                              void* d_out, int out_size) {
    const float* feat   = (const float*)d_in[0];
    const float* attn_w = (const float*)d_in[1];
    const float* attn_b = (const float*)d_in[2];
    const float* proj_w = (const float*)d_in[3];
    const float* proj_b = (const float*)d_in[4];
    const float* ln_g   = (const float*)d_in[5];
    const float* ln_b   = (const float*)d_in[6];
    const int*   m2m    = (const int*)d_in[7];
    int n = in_sizes[7];
    float* out = (float*)d_out;

    static bool attr_done = false;
    if (!attr_done) {
        cudaFuncSetAttribute(gemm_mma_kernel,
                             cudaFuncAttributeMaxDynamicSharedMemorySize, SMEM_GEMM);
        attr_done = true;
    }

    init_wsplit_kernel<<<(MICRO_DIM * MICRO_DIM) / 256, 256>>>(proj_w);
    count_kernel<<<(n + 255) / 256, 256>>>(m2m, n);
    sum_chunks_kernel<<<NB_CHUNK, 256>>>();
    scan_bsums_kernel<<<1, 32>>>();
    scan_chunks_kernel<<<NB_CHUNK, 32>>>();
    scatter_kernel<<<(n + 255) / 256, 256>>>(m2m, n);
    agg_kernel<<<NSEG, 256>>>(feat, attn_w, attn_b);

    dim3 ggrid(MICRO_DIM / GTILE_N, NSEG_PAD / GTILE_M);   // (2, 469)
    gemm_mma_kernel<<<ggrid, 512, SMEM_GEMM>>>(out, NSEG);

    ln_gelu_kernel<<<(NSEG + 7) / 8, 256>>>(proj_b, ln_g, ln_b, out, NSEG);
}

// round 8
// speedup vs baseline: 1.4508x; 1.2696x over previous
#include <cuda_runtime.h>
#include <cuda_bf16.h>
#include <math.h>
#include <stdint.h>

// ---------------- problem constants ----------------
#define N_MICRO_MAX 500000
#define MICRO_DIM   512
#define N_NODES_C   20000
#define N_EDGES_C   40000
#define NSEG        60000
#define NSEG_PAD    60032          // 469 * 128
#define EPS_SM      1e-8f
#define EPS_LN      1e-5f

#define CHUNK       1024
#define NB_CHUNK    59

// ---------------- device scratch ----------------
__device__ int   g_counts[NSEG];
__device__ int   g_offsets[NSEG];
__device__ int   g_cursor[NSEG];
__device__ int   g_bsum[NB_CHUNK];
__device__ int   g_rows[N_MICRO_MAX];
__device__ __align__(128) __nv_bfloat16 g_a_hi[(size_t)NSEG_PAD * MICRO_DIM];  // A bf16 hi (zero-init pad)
__device__ __align__(128) __nv_bfloat16 g_a_lo[(size_t)NSEG_PAD * MICRO_DIM];  // A bf16 lo
__device__ __align__(128) __nv_bfloat16 g_wt_hi[MICRO_DIM * MICRO_DIM];        // W^T [N][K], bf16 hi
__device__ __align__(128) __nv_bfloat16 g_wt_lo[MICRO_DIM * MICRO_DIM];        // W^T [N][K], bf16 lo

// ---------------- helpers ----------------
__device__ __forceinline__ uint32_t smem_u32(const void* p) {
    uint32_t a;
    asm("{ .reg .u64 t; cvta.to.shared.u64 t, %1; cvt.u32.u64 %0, t; }" : "=r"(a) : "l"(p));
    return a;
}

__device__ __forceinline__ int seg_of(int m) {
    if (m >= 0) return m;
    if (m == -100) return -1;
    return N_NODES_C + (-m - 1);
}

__device__ __forceinline__ void ldsm4(uint32_t* r, uint32_t addr) {
    asm volatile("ldmatrix.sync.aligned.m8n8.x4.shared.b16 {%0,%1,%2,%3}, [%4];"
        : "=r"(r[0]), "=r"(r[1]), "=r"(r[2]), "=r"(r[3]) : "r"(addr));
}

__device__ __forceinline__ void mma_bf16(float* d, const uint32_t* a, const uint32_t* b) {
    asm volatile("mma.sync.aligned.m16n8k16.row.col.f32.bf16.bf16.f32 "
        "{%0,%1,%2,%3},{%4,%5,%6,%7},{%8,%9},{%0,%1,%2,%3};"
        : "+f"(d[0]), "+f"(d[1]), "+f"(d[2]), "+f"(d[3])
        : "r"(a[0]), "r"(a[1]), "r"(a[2]), "r"(a[3]), "r"(b[0]), "r"(b[1]));
}

#define CP_ASYNC16(dst, src) \
    asm volatile("cp.async.cg.shared.global [%0], [%1], 16;" :: "r"(dst), "l"(src))
#define CP_COMMIT() asm volatile("cp.async.commit_group;" ::: "memory")
#define CP_WAITG(n) asm volatile("cp.async.wait_group %0;" :: "n"(n) : "memory")

__device__ __forceinline__ float gelu_exact(float y) {
    return 0.5f * y * (1.f + erff(y * 0.70710678118654752f));
}

// ---------------- 0) init scratch + W transpose/split (merged) ----------------
__global__ void init_wsplit_kernel(const float* __restrict__ W) {
    int i = blockIdx.x * blockDim.x + threadIdx.x;   // 0 .. 262143
    if (i < NSEG) { g_counts[i] = 0; g_cursor[i] = 0; }
    int k = i >> 9, n = i & 511;
    float v = W[i];
    __nv_bfloat16 hi = __float2bfloat16_rn(v);
    __nv_bfloat16 lo = __float2bfloat16_rn(v - __bfloat162float(hi));
    g_wt_hi[n * MICRO_DIM + k] = hi;
    g_wt_lo[n * MICRO_DIM + k] = lo;
}

// ---------------- 1) count ----------------
__global__ void count_kernel(const int* __restrict__ m2m, int n) {
    int i = blockIdx.x * blockDim.x + threadIdx.x;
    if (i < n) {
        int s = seg_of(m2m[i]);
        if (s >= 0) atomicAdd(&g_counts[s], 1);
    }
}

// ---------------- 2) scan ----------------
__global__ void sum_chunks_kernel() {
    __shared__ int sh[256];
    int b = blockIdx.x, t = threadIdx.x;
    int base = b * CHUNK;
    int s = 0;
    for (int j = t; j < CHUNK; j += 256) {
        int i = base + j;
        if (i < NSEG) s += g_counts[i];
    }
    sh[t] = s; __syncthreads();
    for (int d = 128; d; d >>= 1) { if (t < d) sh[t] += sh[t + d]; __syncthreads(); }
    if (t == 0) g_bsum[b] = sh[0];
}

__global__ void scan_bsums_kernel() {
    if (threadIdx.x == 0 && blockIdx.x == 0) {
        int c = 0;
        for (int b = 0; b < NB_CHUNK; b++) { int v = g_bsum[b]; g_bsum[b] = c; c += v; }
    }
}

__global__ void scan_chunks_kernel() {
    int b = blockIdx.x, lane = threadIdx.x;
    int base = b * CHUNK + lane * 32;
    int vals[32];
    int lsum = 0;
    #pragma unroll
    for (int j = 0; j < 32; j++) {
        int i = base + j;
        vals[j] = (i < NSEG) ? g_counts[i] : 0;
        lsum += vals[j];
    }
    int pre = lsum;
    #pragma unroll
    for (int d = 1; d < 32; d <<= 1) {
        int x = __shfl_up_sync(0xffffffffu, pre, d);
        if (lane >= d) pre += x;
    }
    pre -= lsum;
    int carry = g_bsum[b] + pre;
    #pragma unroll
    for (int j = 0; j < 32; j++) {
        int i = base + j;
        if (i < NSEG) g_offsets[i] = carry;
        carry += vals[j];
    }
}

// ---------------- 3) scatter ----------------
__global__ void scatter_kernel(const int* __restrict__ m2m, int n) {
    int i = blockIdx.x * blockDim.x + threadIdx.x;
    if (i < n) {
        int s = seg_of(m2m[i]);
        if (s >= 0) {
            int pos = g_offsets[s] + atomicAdd(&g_cursor[s], 1);
            g_rows[pos] = i;
        }
    }
}

// ---------------- 4) warp-per-segment online-softmax aggregation ----------------
// One warp owns one segment: stream its rows once, online softmax in registers,
// no block barriers, feature bytes read exactly once.
__global__ void __launch_bounds__(256)
agg_warp_kernel(const float* __restrict__ feat,
                const float* __restrict__ attn_w,
                const float* __restrict__ attn_bp) {
    int wid  = threadIdx.x >> 5;
    int lane = threadIdx.x & 31;
    int seg  = blockIdx.x * 8 + wid;
    if (seg >= NSEG) return;

    int cnt = g_counts[seg];
    int off = g_offsets[seg];
    size_t outbase = (size_t)seg * MICRO_DIM;

    // lane owns float4 groups fi = lane + 32*k (cols 4*fi .. 4*fi+3)
    if (cnt == 0) {
        uint2 z = make_uint2(0u, 0u);
        #pragma unroll
        for (int k = 0; k < 4; k++) {
            int fi = lane + 32 * k;
            *(uint2*)(g_a_hi + outbase + fi * 4) = z;
            *(uint2*)(g_a_lo + outbase + fi * 4) = z;
        }
        return;
    }

    float4 aw[4];
    #pragma unroll
    for (int k = 0; k < 4; k++) aw[k] = ((const float4*)attn_w)[lane + 32 * k];
    float ab = attn_bp[0];

    float m = -INFINITY, s = 0.f;
    float acc[16];
    #pragma unroll
    for (int i = 0; i < 16; i++) acc[i] = 0.f;

    // prefetch row 0
    int row = g_rows[off];
    float4 v[4];
    #pragma unroll
    for (int k = 0; k < 4; k++)
        v[k] = ((const float4*)(feat + (size_t)row * MICRO_DIM))[lane + 32 * k];

    for (int r = 0; r < cnt; r++) {
        float4 cur[4];
        #pragma unroll
        for (int k = 0; k < 4; k++) cur[k] = v[k];

        if (r + 1 < cnt) {                       // prefetch next row
            int nrow = g_rows[off + r + 1];
            #pragma unroll
            for (int k = 0; k < 4; k++)
                v[k] = ((const float4*)(feat + (size_t)nrow * MICRO_DIM))[lane + 32 * k];
        }

        float dot = 0.f;
        #pragma unroll
        for (int k = 0; k < 4; k++)
            dot += cur[k].x * aw[k].x + cur[k].y * aw[k].y
                 + cur[k].z * aw[k].z + cur[k].w * aw[k].w;
        #pragma unroll
        for (int d = 16; d; d >>= 1) dot += __shfl_xor_sync(0xffffffffu, dot, d);
        float l = dot + ab;

        float mn = fmaxf(m, l);
        float sc = expf(m - mn);
        float e  = expf(l - mn);
        #pragma unroll
        for (int k = 0; k < 4; k++) {
            acc[4*k+0] = acc[4*k+0] * sc + e * cur[k].x;
            acc[4*k+1] = acc[4*k+1] * sc + e * cur[k].y;
            acc[4*k+2] = acc[4*k+2] * sc + e * cur[k].z;
            acc[4*k+3] = acc[4*k+3] * sc + e * cur[k].w;
        }
        s = s * sc + e;
        m = mn;
    }

    float inv = 1.f / (s + EPS_SM);
    #pragma unroll
    for (int k = 0; k < 4; k++) {
        int fi = lane + 32 * k;
        float f0 = acc[4*k+0] * inv, f1 = acc[4*k+1] * inv;
        float f2 = acc[4*k+2] * inv, f3 = acc[4*k+3] * inv;
        __nv_bfloat162 h01 = __floats2bfloat162_rn(f0, f1);
        __nv_bfloat162 h23 = __floats2bfloat162_rn(f2, f3);
        __nv_bfloat162 l01 = __floats2bfloat162_rn(f0 - __bfloat162float(h01.x),
                                                   f1 - __bfloat162float(h01.y));
        __nv_bfloat162 l23 = __floats2bfloat162_rn(f2 - __bfloat162float(h23.x),
                                                   f3 - __bfloat162float(h23.y));
        *(uint2*)(g_a_hi + outbase + fi * 4) = make_uint2(*(uint32_t*)&h01, *(uint32_t*)&h23);
        *(uint2*)(g_a_lo + outbase + fi * 4) = make_uint2(*(uint32_t*)&l01, *(uint32_t*)&l23);
    }
}

// ---------------- 5) mma.sync bf16 3-split GEMM, 128x256 tile, 3-stage cp.async ----------------
#define GTILE_M   128
#define GTILE_N   256
#define GKC       32
#define GNCHUNK   16
#define ROWB      80
#define A_MAT     (128 * ROWB)       // 10240
#define B_MAT     (256 * ROWB)       // 20480
#define AHI_OFF   0
#define ALO_OFF   A_MAT
#define BHI_OFF   (2 * A_MAT)
#define BLO_OFF   (2 * A_MAT + B_MAT)
#define STAGE_SZ  (2 * A_MAT + 2 * B_MAT)   // 61440
#define NSTAGE    3
#define SMEM_GEMM (NSTAGE * STAGE_SZ)       // 184320

__global__ void __launch_bounds__(512, 1)
gemm_mma_kernel(float* __restrict__ out, int M) {
    extern __shared__ char smem[];
    uint32_t sbase = smem_u32(smem);

    int tid  = threadIdx.x;
    int lane = tid & 31, wid = tid >> 5;
    int warp_m = wid & 3;          // 32-row slice
    int warp_n = wid >> 2;         // 64-col slice (0..3)
    int rowBase = blockIdx.y * GTILE_M;
    int colBase = blockIdx.x * GTILE_N;

    float acc[2][8][4];
    #pragma unroll
    for (int i = 0; i < 2; i++)
        #pragma unroll
        for (int j = 0; j < 8; j++)
            #pragma unroll
            for (int q = 0; q < 4; q++) acc[i][j][q] = 0.f;

    #define G_ISSUE(c) do {                                                           \
        uint32_t sb_ = sbase + ((c) % NSTAGE) * STAGE_SZ;                             \
        int k0_ = (c) * GKC;                                                          \
        _Pragma("unroll")                                                             \
        for (int i_ = 0; i_ < 2; i_++) {                                              \
            int f_ = tid + i_ * 512;                                                  \
            int mat_ = f_ >> 9;  int w_ = f_ & 511;                                   \
            int r_ = w_ >> 2, q_ = w_ & 3;                                            \
            const __nv_bfloat16* s_ = (mat_ ? g_a_lo : g_a_hi)                        \
                + (size_t)(rowBase + r_) * MICRO_DIM + q_ * 8 + k0_;                  \
            CP_ASYNC16(sb_ + mat_ * A_MAT + r_ * ROWB + q_ * 16, s_);                 \
        }                                                                             \
        _Pragma("unroll")                                                             \
        for (int i_ = 0; i_ < 4; i_++) {                                              \
            int f_ = tid + i_ * 512;                                                  \
            int mat_ = f_ >> 10; int w_ = f_ & 1023;                                  \
            int r_ = w_ >> 2, q_ = w_ & 3;                                            \
            const __nv_bfloat16* s_ = (mat_ ? g_wt_lo : g_wt_hi)                      \
                + (size_t)(colBase + r_) * MICRO_DIM + q_ * 8 + k0_;                  \
            CP_ASYNC16(sb_ + BHI_OFF + mat_ * B_MAT + r_ * ROWB + q_ * 16, s_);       \
        }                                                                             \
        CP_COMMIT();                                                                  \
    } while (0)

    int a_r = (lane & 7) + ((lane >> 3) & 1) * 8;
    int a_o = (lane >> 4) * 16;
    int b_r = (lane & 7) + ((lane >> 4) & 1) * 8;
    int b_o = ((lane >> 3) & 1) * 16;

    G_ISSUE(0);
    G_ISSUE(1);

    for (int c = 0; c < GNCHUNK; c++) {
        CP_WAITG(1);
        __syncthreads();

        uint32_t stage = sbase + (c % NSTAGE) * STAGE_SZ;
        #pragma unroll
        for (int s = 0; s < 2; s++) {
            uint32_t ah[2][4], al[2][4];
            #pragma unroll
            for (int mm = 0; mm < 2; mm++) {
                uint32_t off = (uint32_t)((warp_m * 32 + mm * 16 + a_r) * ROWB + s * 32 + a_o);
                ldsm4(ah[mm], stage + AHI_OFF + off);
                ldsm4(al[mm], stage + ALO_OFF + off);
            }
            #pragma unroll
            for (int p = 0; p < 4; p++) {
                uint32_t bh[4], bl[4];
                uint32_t off = (uint32_t)((warp_n * 64 + p * 16 + b_r) * ROWB + s * 32 + b_o);
                ldsm4(bh, stage + BHI_OFF + off);
                ldsm4(bl, stage + BLO_OFF + off);
                #pragma unroll
                for (int mm = 0; mm < 2; mm++) {
                    #pragma unroll
                    for (int h = 0; h < 2; h++) {
                        float* a4 = acc[mm][2 * p + h];
                        mma_bf16(a4, ah[mm], &bh[h * 2]);
                        mma_bf16(a4, ah[mm], &bl[h * 2]);
                        mma_bf16(a4, al[mm], &bh[h * 2]);
                    }
                }
            }
        }
        if (c + 2 < GNCHUNK) G_ISSUE(c + 2);
    }

    #pragma unroll
    for (int mm = 0; mm < 2; mm++) {
        int row0 = rowBase + warp_m * 32 + mm * 16 + (lane >> 2);
        #pragma unroll
        for (int nt = 0; nt < 8; nt++) {
            int col = colBase + warp_n * 64 + nt * 8 + (lane & 3) * 2;
            if (row0 < M)
                *(float2*)(out + (size_t)row0 * MICRO_DIM + col) =
                    make_float2(acc[mm][nt][0], acc[mm][nt][1]);
            if (row0 + 8 < M)
                *(float2*)(out + (size_t)(row0 + 8) * MICRO_DIM + col) =
                    make_float2(acc[mm][nt][2], acc[mm][nt][3]);
        }
    }
    #undef G_ISSUE
}

// ---------------- 6) bias + LayerNorm + exact GELU ----------------
__global__ void __launch_bounds__(256)
ln_gelu_kernel(const float* __restrict__ pb,
               const float* __restrict__ lng,
               const float* __restrict__ lnb,
               float* __restrict__ out, int M) {
    int row  = blockIdx.x * 8 + (threadIdx.x >> 5);
    int lane = threadIdx.x & 31;
    if (row >= M) return;

    float4* p = (float4*)(out + (size_t)row * MICRO_DIM);
    const float4* pb4 = (const float4*)pb;
    float x[16];
    float sum = 0.f;
    #pragma unroll
    for (int k = 0; k < 4; k++) {
        float4 h = p[lane + 32 * k];
        float4 b = pb4[lane + 32 * k];
        x[4*k+0] = h.x + b.x; x[4*k+1] = h.y + b.y;
        x[4*k+2] = h.z + b.z; x[4*k+3] = h.w + b.w;
        sum += x[4*k] + x[4*k+1] + x[4*k+2] + x[4*k+3];
    }
    #pragma unroll
    for (int d = 16; d; d >>= 1) sum += __shfl_xor_sync(0xffffffffu, sum, d);
    float mu = sum * (1.f / 512.f);

    float v = 0.f;
    #pragma unroll
    for (int i = 0; i < 16; i++) { float dlt = x[i] - mu; v += dlt * dlt; }
    #pragma unroll
    for (int d = 16; d; d >>= 1) v += __shfl_xor_sync(0xffffffffu, v, d);
    v *= (1.f / 512.f);
    float rs = rsqrtf(v + EPS_LN);

    const float4* g4 = (const float4*)lng;
    const float4* b4 = (const float4*)lnb;
    #pragma unroll
    for (int k = 0; k < 4; k++) {
        float4 gg = g4[lane + 32 * k];
        float4 bb = b4[lane + 32 * k];
        float4 o;
        float y;
        y = (x[4*k+0] - mu) * rs * gg.x + bb.x; o.x = gelu_exact(y);
        y = (x[4*k+1] - mu) * rs * gg.y + bb.y; o.y = gelu_exact(y);
        y = (x[4*k+2] - mu) * rs * gg.z + bb.z; o.z = gelu_exact(y);
        y = (x[4*k+3] - mu) * rs * gg.w + bb.w; o.w = gelu_exact(y);
        p[lane + 32 * k] = o;
    }
}

// ---------------- launch ----------------
extern "C" void kernel_launch(void* const* d_in, const int* in_sizes, int n_in,
                              void* d_out, int out_size) {
    const float* feat   = (const float*)d_in[0];
    const float* attn_w = (const float*)d_in[1];
    const float* attn_b = (const float*)d_in[2];
    const float* proj_w = (const float*)d_in[3];
    const float* proj_b = (const float*)d_in[4];
    const float* ln_g   = (const float*)d_in[5];
    const float* ln_b   = (const float*)d_in[6];
    const int*   m2m    = (const int*)d_in[7];
    int n = in_sizes[7];
    float* out = (float*)d_out;

    static bool attr_done = false;
    if (!attr_done) {
        cudaFuncSetAttribute(gemm_mma_kernel,
                             cudaFuncAttributeMaxDynamicSharedMemorySize, SMEM_GEMM);
        attr_done = true;
    }

    init_wsplit_kernel<<<(MICRO_DIM * MICRO_DIM) / 256, 256>>>(proj_w);
    count_kernel<<<(n + 255) / 256, 256>>>(m2m, n);
    sum_chunks_kernel<<<NB_CHUNK, 256>>>();
    scan_bsums_kernel<<<1, 32>>>();
    scan_chunks_kernel<<<NB_CHUNK, 32>>>();
    scatter_kernel<<<(n + 255) / 256, 256>>>(m2m, n);
    agg_warp_kernel<<<(NSEG + 7) / 8, 256>>>(feat, attn_w, attn_b);

    dim3 ggrid(MICRO_DIM / GTILE_N, NSEG_PAD / GTILE_M);   // (2, 469)
    gemm_mma_kernel<<<ggrid, 512, SMEM_GEMM>>>(out, NSEG);

    ln_gelu_kernel<<<(NSEG + 7) / 8, 256>>>(proj_b, ln_g, ln_b, out, NSEG);
}